// round 6
// baseline (speedup 1.0000x reference)
#include <cuda_runtime.h>
#include <cstdint>

#define HW 4096
#define PP 441
#define NPAIR 28

typedef unsigned int u32;
typedef unsigned long long ull;

__device__ __align__(16) float g_cor[(size_t)NPAIR * PP * HW];
__device__ float g_stat[2 * PP];               // [0..440] sum, [441..881] sumsq
__device__ __align__(16) float g_w2t[PP * 64];
__device__ float g_bias[64];

__device__ __forceinline__ void cpa16(u32 dst, const void* src, bool v) {
    int sz = v ? 16 : 0;
    asm volatile("cp.async.cg.shared.global [%0], [%1], 16, %2;\n" :: "r"(dst), "l"(src), "r"(sz));
}
__device__ __forceinline__ void cpa_commit() { asm volatile("cp.async.commit_group;\n"); }
template <int N> __device__ __forceinline__ void cpa_wait() {
    asm volatile("cp.async.wait_group %0;\n" :: "n"(N));
}
__device__ __forceinline__ void fma2(ull& d, ull a, ull b) {
    asm("fma.rn.f32x2 %0, %1, %2, %0;" : "+l"(d) : "l"(a), "l"(b));
}
__device__ __forceinline__ ull dup2(float x) {
    ull d; u32 xi = __float_as_uint(x);
    asm("mov.b64 %0, {%1, %1};" : "=l"(d) : "r"(xi));
    return d;
}
__device__ __forceinline__ void unpk(float& lo, float& hi, ull v) {
    asm("mov.b64 {%0, %1}, %2;" : "=f"(lo), "=f"(hi) : "l"(v));
}
__device__ __forceinline__ int swzu(int u) { return u ^ ((u >> 3) & 1); }

// ---------------------------------------------------------------------------
// corr v4: grid (8 h-tiles, 3 p-thirds, 28 pairs), 128 thr. smem 188416 B.
//   f2 double buffer: 2 x [8c][8r][112w] = 2 x 7168 floats
//   f1 resident:      [64c][8r][64w swizzled] = 32768 floats (loaded once)
// Thread (qh=tid>>6, h=(tid>>3)&7, wg=tid&7): 8w x 11q tile per p.
// Stats (sum, sumsq per p*21+q channel) fused via shuffle + atomicAdd.
// ---------------------------------------------------------------------------
#define F2CH 896
#define F2SZ 7168
#define F1BASE 14336
#define CORR_SMEM ((14336 + 32768) * 4)

__global__ void __launch_bounds__(128) corr_kernel(const float* __restrict__ feats) {
    extern __shared__ float sm[];
    const int tid = threadIdx.x;
    const int n = blockIdx.z, pr0 = blockIdx.y * 7, h0 = blockIdx.x * 8;
    const int bb = n / 7, tt = n % 7;
    const float* f1f = feats + (size_t)(bb * 8 + tt) * 64 * HW;
    const float* f2f = f1f + (size_t)64 * HW;
    const u32 smb = (u32)__cvta_generic_to_shared(sm);

    // zero f2 border units (both buffers; staging never writes them)
    for (int idx = tid; idx < 1536; idx += 128) {
        int bf = idx / 768, rem = idx % 768;
        int c = rem / 96, r2 = rem % 96, r = r2 / 12, k = r2 % 12;
        int u = (k < 5) ? k : k + 16;
        float4* p = reinterpret_cast<float4*>(sm + bf * F2SZ + c * F2CH + r * 112) + swzu(u);
        *p = make_float4(0.f, 0.f, 0.f, 0.f);
    }

    // load f1 resident: 8192 units, 64 per thread
#pragma unroll
    for (int i = 0; i < 64; ++i) {
        int idx = tid + i * 128;
        int c = idx >> 7, r = (idx >> 4) & 7, uu = idx & 15;
        cpa16(smb + (u32)(F1BASE + c * 512 + r * 64 + swzu(uu) * 4) * 4u,
              f1f + (size_t)c * HW + (h0 + r) * 64 + uu * 4, true);
    }

    const int qh = tid >> 6, h = (tid >> 3) & 7, wg = tid & 7;

    auto issue = [&](int s, int bf) {
        const int p = pr0 + (s >> 3), c0 = (s & 7) * 8, dy = 2 * p - 20;
        const u32 bbase = smb + (u32)(bf * F2SZ) * 4u;
#pragma unroll
        for (int i = 0; i < 8; ++i) {  // f2: 1024 units
            int idx = tid + i * 128;
            int c = idx >> 7, r = (idx >> 4) & 7, uu = idx & 15;
            int row = h0 + r + dy;
            bool v = (unsigned)row < 64u;
            int rc = v ? row : 0;
            cpa16(bbase + (u32)(c * F2CH + r * 112 + swzu(5 + uu) * 4) * 4u,
                  f2f + (size_t)(c0 + c) * HW + rc * 64 + uu * 4, v);
        }
        cpa_commit();
    };

    const int o1a = h * 64 + swzu(wg * 2) * 4;
    const int o1b = h * 64 + swzu(wg * 2 + 1) * 4;
    int om[7];
#pragma unroll
    for (int m = 0; m < 7; ++m) om[m] = h * 112 + swzu(wg * 2 + 5 * qh + m) * 4;

    const int NS = 56;
    ull acc2[11][4];
    issue(0, 0);   // note: f1 loads are in this first commit group too

    for (int s = 0; s < NS; ++s) {
        const int bf = s & 1, ck = s & 7;
        cpa_wait<0>();
        __syncthreads();
        if (s + 1 < NS) issue(s + 1, bf ^ 1);
        if (ck == 0) {
#pragma unroll
            for (int j = 0; j < 11; ++j)
#pragma unroll
                for (int k2 = 0; k2 < 4; ++k2) acc2[j][k2] = 0ull;
        }
        const float* f1b = sm + F1BASE + (s & 7) * 8 * 512;
        const float* f2b = sm + bf * F2SZ;
#pragma unroll 2
        for (int c = 0; c < 8; ++c) {
            ulonglong2 xa = *reinterpret_cast<const ulonglong2*>(f1b + c * 512 + o1a);
            ulonglong2 xb = *reinterpret_cast<const ulonglong2*>(f1b + c * 512 + o1b);
            ull a2[4] = {xa.x, xa.y, xb.x, xb.y};
#pragma unroll
            for (int m = 0; m < 7; ++m) {
                ulonglong2 t = *reinterpret_cast<const ulonglong2*>(f2b + c * F2CH + om[m]);
#pragma unroll
                for (int k2 = 0; k2 < 4; ++k2) {
                    const int j0 = 2 * m - k2;
                    const int j1 = 2 * m + 1 - k2;
                    if (j0 >= 0 && j0 <= 10) fma2(acc2[j0][k2], a2[k2], t.x);
                    if (j1 >= 0 && j1 <= 10) fma2(acc2[j1][k2], a2[k2], t.y);
                }
            }
        }
        if (ck == 7) {
            const int p = pr0 + (s >> 3);
            // stores
            float* outp = g_cor + ((size_t)n * PP + (size_t)(p * 21 + 10 * qh)) * HW
                          + (h0 + h) * 64 + wg * 8;
            for (int j = (qh ? 1 : 0); j < 11; ++j) {
                ulonglong2 v0, v1;
                v0.x = acc2[j][0]; v0.y = acc2[j][1];
                v1.x = acc2[j][2]; v1.y = acc2[j][3];
                *reinterpret_cast<ulonglong2*>(outp + (size_t)j * HW)     = v0;
                *reinterpret_cast<ulonglong2*>(outp + (size_t)j * HW + 4) = v1;
            }
            // fused stats: per-q sum and sumsq, warp butterfly, atomicAdd
            const int lane = tid & 31;
            for (int j = (qh ? 1 : 0); j < 11; ++j) {
                float s1 = 0.f, s2v = 0.f;
#pragma unroll
                for (int k2 = 0; k2 < 4; ++k2) {
                    float lo, hi;
                    unpk(lo, hi, acc2[j][k2]);
                    s1 += lo + hi;
                    s2v += lo * lo + hi * hi;
                }
#pragma unroll
                for (int ofs = 1; ofs < 32; ofs <<= 1) {
                    s1  += __shfl_xor_sync(0xffffffffu, s1, ofs);
                    s2v += __shfl_xor_sync(0xffffffffu, s2v, ofs);
                }
                if (lane == 0) {
                    int q = p * 21 + 10 * qh + j;
                    atomicAdd(&g_stat[q], s1);
                    atomicAdd(&g_stat[PP + q], s2v);
                }
            }
        }
    }
}

// ---------------------------------------------------------------------------
__global__ void zero_stat_kernel() {
    int i = threadIdx.x;
    if (i < 2 * PP) g_stat[i] = 0.f;
}

// ---------------------------------------------------------------------------
__global__ void __launch_bounds__(256) fold_kernel(const float* __restrict__ gamma,
                                                   const float* __restrict__ beta,
                                                   const float* __restrict__ convw) {
    __shared__ float ssc[PP], ssh[PP];
    const int tid = threadIdx.x;
    const float inv = 1.f / (float)(NPAIR * HW);
    for (int p = tid; p < PP; p += 256) {
        float mean = g_stat[p] * inv;
        float var  = g_stat[PP + p] * inv - mean * mean;
        float rstd = rsqrtf(var + 1e-5f);
        float sc = gamma[p] * rstd;
        ssc[p] = sc;
        ssh[p] = beta[p] - sc * mean;
    }
    __syncthreads();
    for (int idx = tid; idx < PP * 64; idx += 256) {
        int p = idx >> 6, o = idx & 63;
        g_w2t[idx] = convw[o * PP + p] * ssc[p];
    }
    if (tid < 64) {
        float bs = 0.f;
        for (int p = 0; p < PP; ++p) bs += convw[tid * PP + p] * ssh[p];
        g_bias[tid] = bs;
    }
}

// ---------------------------------------------------------------------------
// conv: grid (64 px-tiles, 28), 128 thr. 64px x 64out, K=441 in 21-chunks,
// depth-3 cp.async pipeline, single sync per chunk.
// ---------------------------------------------------------------------------
__global__ void __launch_bounds__(128) conv_kernel(float* __restrict__ out) {
    __shared__ float As[3][21 * 64];
    __shared__ float Bs[3][21 * 64];
    const int tid = threadIdx.x, n = blockIdx.y, px0 = blockIdx.x * 64;
    const int og = tid >> 4, pxg = tid & 15;
    const float* corn = g_cor + (size_t)n * PP * HW;
    const u32 sa = (u32)__cvta_generic_to_shared(As);
    const u32 sb = (u32)__cvta_generic_to_shared(Bs);

    auto issue = [&](int pc, int bf) {
#pragma unroll
        for (int i = 0; i < 6; ++i) {
            int idx = tid + i * 128;
            if (idx < 672) {
                int half = idx >= 336;
                int id2 = half ? idx - 336 : idx;
                int c = id2 >> 4, u = id2 & 15;
                if (!half)
                    cpa16(sa + (u32)(bf * 1344 + c * 64 + u * 4) * 4u,
                          corn + (size_t)(pc * 21 + c) * HW + px0 + u * 4, true);
                else
                    cpa16(sb + (u32)(bf * 1344 + c * 64 + u * 4) * 4u,
                          g_w2t + (pc * 21 + c) * 64 + u * 4, true);
            }
        }
        cpa_commit();
    };

    ull acc2[4][4];
#pragma unroll
    for (int s2 = 0; s2 < 4; ++s2)
#pragma unroll
        for (int r = 0; r < 4; ++r) acc2[s2][r] = 0ull;

    issue(0, 0);
    issue(1, 1);
    for (int pc = 0; pc < 21; ++pc) {
        const int bf = pc % 3;
        if (pc >= 19) cpa_wait<0>(); else cpa_wait<1>();
        __syncthreads();
        if (pc + 2 < 21) issue(pc + 2, (pc + 2) % 3);
#pragma unroll
        for (int i = 0; i < 21; ++i) {
            float4 a = *reinterpret_cast<const float4*>(&As[bf][i * 64 + pxg * 4]);
            ulonglong2 b01 = *reinterpret_cast<const ulonglong2*>(&Bs[bf][i * 64 + og * 8]);
            ulonglong2 b23 = *reinterpret_cast<const ulonglong2*>(&Bs[bf][i * 64 + og * 8 + 4]);
            ull b2[4] = {b01.x, b01.y, b23.x, b23.y};
            ull avd[4] = {dup2(a.x), dup2(a.y), dup2(a.z), dup2(a.w)};
#pragma unroll
            for (int s2 = 0; s2 < 4; ++s2)
#pragma unroll
                for (int r = 0; r < 4; ++r)
                    fma2(acc2[s2][r], avd[r], b2[s2]);
        }
    }

    const int b = n / 7, t = n % 7;
    float* outn = out + (size_t)(b * 8 + t) * 64 * HW + px0 + pxg * 4;
#pragma unroll
    for (int s2 = 0; s2 < 4; ++s2) {
        float lo[4], hi[4];
#pragma unroll
        for (int r = 0; r < 4; ++r) unpk(lo[r], hi[r], acc2[s2][r]);
        const float bo0 = g_bias[og * 8 + 2 * s2];
        const float bo1 = g_bias[og * 8 + 2 * s2 + 1];
        float4 v0 = make_float4(lo[0] + bo0, lo[1] + bo0, lo[2] + bo0, lo[3] + bo0);
        float4 v1 = make_float4(hi[0] + bo1, hi[1] + bo1, hi[2] + bo1, hi[3] + bo1);
        *reinterpret_cast<float4*>(outn + (size_t)(og * 8 + 2 * s2) * HW)     = v0;
        *reinterpret_cast<float4*>(outn + (size_t)(og * 8 + 2 * s2 + 1) * HW) = v1;
    }
}

// ---------------------------------------------------------------------------
__global__ void zero_tail_kernel(float* __restrict__ out) {
    int idx = blockIdx.x * 256 + threadIdx.x;
    if (idx < 262144) {
        int b = idx >> 16, r = idx & 65535;
        reinterpret_cast<float4*>(out)[(size_t)(b * 8 + 7) * 64 * 1024 + r] =
            make_float4(0.f, 0.f, 0.f, 0.f);
    }
}

// ---------------------------------------------------------------------------
extern "C" void kernel_launch(void* const* d_in, const int* in_sizes, int n_in,
                              void* d_out, int out_size) {
    const float* feats = (const float*)d_in[0];
    const float* gamma = (const float*)d_in[1];
    const float* beta  = (const float*)d_in[2];
    const float* convw = (const float*)d_in[3];
    float* out = (float*)d_out;

    cudaFuncSetAttribute(corr_kernel, cudaFuncAttributeMaxDynamicSharedMemorySize, CORR_SMEM);

    zero_stat_kernel<<<1, 896>>>();
    corr_kernel<<<dim3(8, 3, 28), 128, CORR_SMEM>>>(feats);
    fold_kernel<<<1, 256>>>(gamma, beta, convw);
    conv_kernel<<<dim3(64, 28), 128>>>(out);
    zero_tail_kernel<<<1024, 256>>>(out);
}

// round 8
// speedup vs baseline: 1.1782x; 1.1782x over previous
#include <cuda_runtime.h>
#include <cstdint>

#define HW 4096
#define PP 441
#define NPAIR 28

typedef unsigned int u32;
typedef unsigned long long ull;

__device__ __align__(16) float g_cor[(size_t)NPAIR * PP * HW];
__device__ float g_stat[2 * PP];               // [0..440] sum, [441..881] sumsq
__device__ __align__(16) float g_w2t[PP * 64];
__device__ float g_bias[64];

__device__ __forceinline__ void cpa16(u32 dst, const void* src, bool v) {
    int sz = v ? 16 : 0;
    asm volatile("cp.async.cg.shared.global [%0], [%1], 16, %2;\n" :: "r"(dst), "l"(src), "r"(sz));
}
__device__ __forceinline__ void cpa_commit() { asm volatile("cp.async.commit_group;\n"); }
template <int N> __device__ __forceinline__ void cpa_wait() {
    asm volatile("cp.async.wait_group %0;\n" :: "n"(N));
}
__device__ __forceinline__ void fma2(ull& d, ull a, ull b) {
    asm("fma.rn.f32x2 %0, %1, %2, %0;" : "+l"(d) : "l"(a), "l"(b));
}
__device__ __forceinline__ ull dup2(float x) {
    ull d; u32 xi = __float_as_uint(x);
    asm("mov.b64 %0, {%1, %1};" : "=l"(d) : "r"(xi));
    return d;
}
__device__ __forceinline__ void unpk(float& lo, float& hi, ull v) {
    asm("mov.b64 {%0, %1}, %2;" : "=f"(lo), "=f"(hi) : "l"(v));
}
__device__ __forceinline__ int swzu(int u) { return u ^ ((u >> 3) & 1); }

// ---------------------------------------------------------------------------
// corr (R5 structure, unchanged pipeline): grid (8,3,28), 128 thr, 90112 B smem,
// 2 blocks/SM. f1 AND f2 staged every stage (distance-2 issue, two syncs).
// Added: fused BN stats (warp butterfly + atomicAdd) at each p epilogue.
// ---------------------------------------------------------------------------
#define F2CH 896
#define F1CH 512
#define F2SZ 7168
#define BUF  11264

__global__ void __launch_bounds__(128) corr_kernel(const float* __restrict__ feats) {
    extern __shared__ float sm[];
    const int tid = threadIdx.x;
    const int n = blockIdx.z, pr0 = blockIdx.y * 7, h0 = blockIdx.x * 8;
    const int bb = n / 7, tt = n % 7;
    const float* f1f = feats + (size_t)(bb * 8 + tt) * 64 * HW;
    const float* f2f = f1f + (size_t)64 * HW;
    const u32 smb = (u32)__cvta_generic_to_shared(sm);

    // zero f2 border units (both buffers)
    for (int idx = tid; idx < 1536; idx += 128) {
        int bf = idx / 768, rem = idx % 768;
        int c = rem / 96, r2 = rem % 96, r = r2 / 12, k = r2 % 12;
        int u = (k < 5) ? k : k + 16;
        float4* p = reinterpret_cast<float4*>(sm + bf * BUF + c * F2CH + r * 112) + swzu(u);
        *p = make_float4(0.f, 0.f, 0.f, 0.f);
    }

    const int qh = tid >> 6, h = (tid >> 3) & 7, wg = tid & 7;

    auto issue = [&](int s, int bf) {
        const int p = pr0 + (s >> 3), c0 = (s & 7) * 8, dy = 2 * p - 20;
        const u32 bbase = smb + (u32)(bf * BUF) * 4u;
#pragma unroll
        for (int i = 0; i < 8; ++i) {  // f2: 1024 units
            int idx = tid + i * 128;
            int c = idx >> 7, r = (idx >> 4) & 7, uu = idx & 15;
            int row = h0 + r + dy;
            bool v = (unsigned)row < 64u;
            int rc = v ? row : 0;
            cpa16(bbase + (u32)(c * F2CH + r * 112 + swzu(5 + uu) * 4) * 4u,
                  f2f + (size_t)(c0 + c) * HW + rc * 64 + uu * 4, v);
        }
#pragma unroll
        for (int i = 0; i < 8; ++i) {  // f1: 1024 units
            int idx = tid + i * 128;
            int c = idx >> 7, r = (idx >> 4) & 7, uu = idx & 15;
            cpa16(bbase + (u32)(F2SZ + c * F1CH + r * 64 + swzu(uu) * 4) * 4u,
                  f1f + (size_t)(c0 + c) * HW + (h0 + r) * 64 + uu * 4, true);
        }
        cpa_commit();
    };

    const int o1a = h * 64 + swzu(wg * 2) * 4;
    const int o1b = h * 64 + swzu(wg * 2 + 1) * 4;
    int om[7];
#pragma unroll
    for (int m = 0; m < 7; ++m) om[m] = h * 112 + swzu(wg * 2 + 5 * qh + m) * 4;

    const int NS = 56;
    ull acc2[11][4];
    issue(0, 0);
    issue(1, 1);

    for (int s = 0; s < NS; ++s) {
        const int bf = s & 1, ck = s & 7;
        if (s == NS - 1) cpa_wait<0>(); else cpa_wait<1>();
        __syncthreads();
        if (ck == 0) {
#pragma unroll
            for (int j = 0; j < 11; ++j)
#pragma unroll
                for (int k2 = 0; k2 < 4; ++k2) acc2[j][k2] = 0ull;
        }
        const float* f1b = sm + bf * BUF + F2SZ;
        const float* f2b = sm + bf * BUF;
#pragma unroll 2
        for (int c = 0; c < 8; ++c) {
            ulonglong2 xa = *reinterpret_cast<const ulonglong2*>(f1b + c * F1CH + o1a);
            ulonglong2 xb = *reinterpret_cast<const ulonglong2*>(f1b + c * F1CH + o1b);
            ull a2[4] = {xa.x, xa.y, xb.x, xb.y};
#pragma unroll
            for (int m = 0; m < 7; ++m) {
                ulonglong2 t = *reinterpret_cast<const ulonglong2*>(f2b + c * F2CH + om[m]);
#pragma unroll
                for (int k2 = 0; k2 < 4; ++k2) {
                    const int j0 = 2 * m - k2;
                    const int j1 = 2 * m + 1 - k2;
                    if (j0 >= 0 && j0 <= 10) fma2(acc2[j0][k2], a2[k2], t.x);
                    if (j1 >= 0 && j1 <= 10) fma2(acc2[j1][k2], a2[k2], t.y);
                }
            }
        }
        __syncthreads();
        if (s + 2 < NS) issue(s + 2, bf);
        if (ck == 7) {
            const int p = pr0 + (s >> 3);
            float* outp = g_cor + ((size_t)n * PP + (size_t)(p * 21 + 10 * qh)) * HW
                          + (h0 + h) * 64 + wg * 8;
            for (int j = (qh ? 1 : 0); j < 11; ++j) {
                ulonglong2 v0, v1;
                v0.x = acc2[j][0]; v0.y = acc2[j][1];
                v1.x = acc2[j][2]; v1.y = acc2[j][3];
                *reinterpret_cast<ulonglong2*>(outp + (size_t)j * HW)     = v0;
                *reinterpret_cast<ulonglong2*>(outp + (size_t)j * HW + 4) = v1;
            }
            // fused BN stats
            const int lane = tid & 31;
            for (int j = (qh ? 1 : 0); j < 11; ++j) {
                float s1 = 0.f, s2v = 0.f;
#pragma unroll
                for (int k2 = 0; k2 < 4; ++k2) {
                    float lo, hi;
                    unpk(lo, hi, acc2[j][k2]);
                    s1 += lo + hi;
                    s2v += lo * lo + hi * hi;
                }
#pragma unroll
                for (int ofs = 1; ofs < 32; ofs <<= 1) {
                    s1  += __shfl_xor_sync(0xffffffffu, s1, ofs);
                    s2v += __shfl_xor_sync(0xffffffffu, s2v, ofs);
                }
                if (lane == 0) {
                    int q = p * 21 + 10 * qh + j;
                    atomicAdd(&g_stat[q], s1);
                    atomicAdd(&g_stat[PP + q], s2v);
                }
            }
        }
    }
}

// ---------------------------------------------------------------------------
__global__ void zero_stat_kernel() {
    int i = threadIdx.x;
    if (i < 2 * PP) g_stat[i] = 0.f;
}

// ---------------------------------------------------------------------------
__global__ void __launch_bounds__(256) fold_kernel(const float* __restrict__ gamma,
                                                   const float* __restrict__ beta,
                                                   const float* __restrict__ convw) {
    __shared__ float ssc[PP], ssh[PP];
    const int tid = threadIdx.x;
    const float inv = 1.f / (float)(NPAIR * HW);
    for (int p = tid; p < PP; p += 256) {
        float mean = g_stat[p] * inv;
        float var  = g_stat[PP + p] * inv - mean * mean;
        float rstd = rsqrtf(var + 1e-5f);
        float sc = gamma[p] * rstd;
        ssc[p] = sc;
        ssh[p] = beta[p] - sc * mean;
    }
    __syncthreads();
    for (int idx = tid; idx < PP * 64; idx += 256) {
        int p = idx >> 6, o = idx & 63;
        g_w2t[idx] = convw[o * PP + p] * ssc[p];
    }
    if (tid < 64) {
        float bs = 0.f;
        for (int p = 0; p < PP; ++p) bs += convw[tid * PP + p] * ssh[p];
        g_bias[tid] = bs;
    }
}

// ---------------------------------------------------------------------------
// conv: grid (64 px-tiles, 28), 128 thr. depth-3 cp.async pipeline.
// ---------------------------------------------------------------------------
__global__ void __launch_bounds__(128) conv_kernel(float* __restrict__ out) {
    __shared__ float As[3][21 * 64];
    __shared__ float Bs[3][21 * 64];
    const int tid = threadIdx.x, n = blockIdx.y, px0 = blockIdx.x * 64;
    const int og = tid >> 4, pxg = tid & 15;
    const float* corn = g_cor + (size_t)n * PP * HW;
    const u32 sa = (u32)__cvta_generic_to_shared(As);
    const u32 sb = (u32)__cvta_generic_to_shared(Bs);

    auto issue = [&](int pc, int bf) {
#pragma unroll
        for (int i = 0; i < 6; ++i) {
            int idx = tid + i * 128;
            if (idx < 672) {
                int half = idx >= 336;
                int id2 = half ? idx - 336 : idx;
                int c = id2 >> 4, u = id2 & 15;
                if (!half)
                    cpa16(sa + (u32)(bf * 1344 + c * 64 + u * 4) * 4u,
                          corn + (size_t)(pc * 21 + c) * HW + px0 + u * 4, true);
                else
                    cpa16(sb + (u32)(bf * 1344 + c * 64 + u * 4) * 4u,
                          g_w2t + (pc * 21 + c) * 64 + u * 4, true);
            }
        }
        cpa_commit();
    };

    ull acc2[4][4];
#pragma unroll
    for (int s2 = 0; s2 < 4; ++s2)
#pragma unroll
        for (int r = 0; r < 4; ++r) acc2[s2][r] = 0ull;

    issue(0, 0);
    issue(1, 1);
    for (int pc = 0; pc < 21; ++pc) {
        const int bf = pc % 3;
        if (pc >= 19) cpa_wait<0>(); else cpa_wait<1>();
        __syncthreads();
        if (pc + 2 < 21) issue(pc + 2, (pc + 2) % 3);
#pragma unroll
        for (int i = 0; i < 21; ++i) {
            float4 a = *reinterpret_cast<const float4*>(&As[bf][i * 64 + pxg * 4]);
            ulonglong2 b01 = *reinterpret_cast<const ulonglong2*>(&Bs[bf][i * 64 + og * 8]);
            ulonglong2 b23 = *reinterpret_cast<const ulonglong2*>(&Bs[bf][i * 64 + og * 8 + 4]);
            ull b2[4] = {b01.x, b01.y, b23.x, b23.y};
            ull avd[4] = {dup2(a.x), dup2(a.y), dup2(a.z), dup2(a.w)};
#pragma unroll
            for (int s2 = 0; s2 < 4; ++s2)
#pragma unroll
                for (int r = 0; r < 4; ++r)
                    fma2(acc2[s2][r], avd[r], b2[s2]);
        }
    }

    const int b = n / 7, t = n % 7;
    float* outn = out + (size_t)(b * 8 + t) * 64 * HW + px0 + pxg * 4;
#pragma unroll
    for (int s2 = 0; s2 < 4; ++s2) {
        float lo[4], hi[4];
#pragma unroll
        for (int r = 0; r < 4; ++r) unpk(lo[r], hi[r], acc2[s2][r]);
        const float bo0 = g_bias[og * 8 + 2 * s2];
        const float bo1 = g_bias[og * 8 + 2 * s2 + 1];
        float4 v0 = make_float4(lo[0] + bo0, lo[1] + bo0, lo[2] + bo0, lo[3] + bo0);
        float4 v1 = make_float4(hi[0] + bo1, hi[1] + bo1, hi[2] + bo1, hi[3] + bo1);
        *reinterpret_cast<float4*>(outn + (size_t)(og * 8 + 2 * s2) * HW)     = v0;
        *reinterpret_cast<float4*>(outn + (size_t)(og * 8 + 2 * s2 + 1) * HW) = v1;
    }
}

// ---------------------------------------------------------------------------
__global__ void zero_tail_kernel(float* __restrict__ out) {
    int idx = blockIdx.x * 256 + threadIdx.x;
    if (idx < 262144) {
        int b = idx >> 16, r = idx & 65535;
        reinterpret_cast<float4*>(out)[(size_t)(b * 8 + 7) * 64 * 1024 + r] =
            make_float4(0.f, 0.f, 0.f, 0.f);
    }
}

// ---------------------------------------------------------------------------
extern "C" void kernel_launch(void* const* d_in, const int* in_sizes, int n_in,
                              void* d_out, int out_size) {
    const float* feats = (const float*)d_in[0];
    const float* gamma = (const float*)d_in[1];
    const float* beta  = (const float*)d_in[2];
    const float* convw = (const float*)d_in[3];
    float* out = (float*)d_out;

    const int corr_smem = 2 * BUF * 4;  // 90112 B
    cudaFuncSetAttribute(corr_kernel, cudaFuncAttributeMaxDynamicSharedMemorySize, corr_smem);

    zero_stat_kernel<<<1, 896>>>();
    corr_kernel<<<dim3(8, 3, 28), 128, corr_smem>>>(feats);
    fold_kernel<<<1, 256>>>(gamma, beta, convw);
    conv_kernel<<<dim3(64, 28), 128>>>(out);
    zero_tail_kernel<<<1024, 256>>>(out);
}